// round 16
// baseline (speedup 1.0000x reference)
#include <cuda_runtime.h>
#include <cuda_bf16.h>

#define SEQ    2048
#define BATCH  64
#define D      256
#define CHUNKS 4
#define CHUNK_S (SEQ / CHUNKS)   // 512
#define HSIZE  4096
#define HMASK  (HSIZE - 1)
#define NT     1024              // 2 CTAs/SM, 64 warps/SM

#define H1 100
#define H2 150

// Scratch (device globals — no allocations allowed; zero-init at load)
__device__ float          g_partial[BATCH * CHUNKS * D];
__device__ int            g_count[BATCH];     // tail ticket; self-resetting
__device__ float          g_w[BATCH * SEQ];   // leader-computed tf*idf weights
__device__ unsigned short g_tok16[BATCH * SEQ];
__device__ int            g_flag[BATCH];      // weights-ready flag; self-resetting
__device__ int            g_done[BATCH];      // follower consume ticket

__device__ __forceinline__ unsigned hash_tok(int tok) {
    return ((unsigned)tok * 2654435761u) & HMASK;
}

__device__ __forceinline__ int ld_acquire(const int* p) {
    int v;
    asm volatile("ld.global.acquire.gpu.b32 %0, [%1];" : "=r"(v) : "l"(p) : "memory");
    return v;
}

// ---------------------------------------------------------------------------
// Single fused kernel. 256 CTAs x 1024 threads, all co-resident (296 slots).
// Leader CTA (chunk 0) of each batch: strided token load + packed histogram
//   (single-CAS fast path) + weights for all 2048 positions -> global,
//   release flag. Followers: acquire-poll flag, read their 512-slice
//   coalesced. All CTAs: gather their chunk; last CTA per batch runs the MLP
//   tail (quad-per-output, direct float4 weight reads).
// ---------------------------------------------------------------------------
__global__ __launch_bounds__(NT, 2)
void fused_kernel(const int*   __restrict__ x,
                  const float* __restrict__ emb,
                  const float* __restrict__ idf,
                  const float* __restrict__ W1, const float* __restrict__ b1,
                  const float* __restrict__ W2, const float* __restrict__ b2,
                  const float* __restrict__ W3, const float* __restrict__ b3,
                  float* __restrict__ out) {
    __shared__ int      tok_sh[SEQ];        // leader: full row; all: [0,512) = gather tokens
    __shared__ unsigned htab[HSIZE];        // packed (tok<<16)|cnt
    __shared__ float    w_sh[CHUNK_S];
    __shared__ float4   red4[16][D / 4];    // 16 KB
    // tail buffers
    __shared__ float4   pls4[D / 4];
    __shared__ float4   h1s4[26];
    __shared__ float    h2s[H2 + 2];
    __shared__ float    zs[2];
    __shared__ int      last_sh;

    const int tid    = threadIdx.x;
    const int b      = blockIdx.x >> 2;     // batch
    const int chunk  = blockIdx.x & 3;      // seq chunk
    const int base   = chunk * CHUNK_S;
    const bool leader = (chunk == 0);

    // ---------------- phase 1: weights ----------------
    if (leader) {
        #pragma unroll
        for (int i = tid; i < HSIZE; i += NT) htab[i] = 0u;
        #pragma unroll
        for (int s = tid; s < SEQ; s += NT) tok_sh[s] = __ldcs(&x[s * BATCH + b]);
        __syncthreads();

        // insert: single-CAS fast path (claim (tok<<16)|1 in one atomic)
        #pragma unroll
        for (int s = tid; s < SEQ; s += NT) {
            int tok = tok_sh[s];
            if (tok == 0) continue;
            unsigned key = (unsigned)tok << 16;
            unsigned h = hash_tok(tok);
            while (true) {
                unsigned prev = atomicCAS(&htab[h], 0u, key | 1u);
                if (prev == 0u) break;
                if ((prev >> 16) == (unsigned)tok) { atomicAdd(&htab[h], 1u); break; }
                h = (h + 1) & HMASK;
            }
        }
        __syncthreads();

        // weights for ALL positions -> global (+ own chunk into smem)
        #pragma unroll
        for (int s = tid; s < SEQ; s += NT) {
            int tok = tok_sh[s];
            float w = 0.0f;
            if (tok != 0) {
                unsigned h = hash_tok(tok);
                unsigned v;
                while (((v = htab[h]) >> 16) != (unsigned)tok) h = (h + 1) & HMASK;
                w = (float)(v & 0xffffu) * __ldg(&idf[tok]);
            }
            g_w[b * SEQ + s]     = w;
            g_tok16[b * SEQ + s] = (unsigned short)tok;
            if (s < CHUNK_S) w_sh[s] = w;   // leader's chunk is [0,512)
        }
        __syncthreads();
        __threadfence();
        if (tid == 0) atomicExch(&g_flag[b], 1);   // release
    } else {
        // follower: wait for leader's weights (acquire poll, 1 thread)
        if (tid == 0) {
            while (ld_acquire(&g_flag[b]) != 1) { }
        }
        __syncthreads();
        // read our 512-slice coalesced
        if (tid < CHUNK_S) {
            tok_sh[tid] = (int)g_tok16[b * SEQ + base + tid];
            w_sh[tid]   = g_w[b * SEQ + base + tid];
        }
        __syncthreads();
        // consume ticket: last of the 3 followers resets flag for next replay
        if (tid == 0) {
            int prev = atomicAdd(&g_done[b], 1);
            if (prev == 2) { g_done[b] = 0; g_flag[b] = 0; }
        }
    }

    // ---------------- phase 2: gather ----------------
    {
        const int sg = tid >> 6;             // 0..15
        const int dq = tid & 63;             // float4 index within row
        const float4* emb4 = reinterpret_cast<const float4*>(emb);

        float4 acc = make_float4(0.f, 0.f, 0.f, 0.f);
        #pragma unroll 4
        for (int s = sg; s < CHUNK_S; s += 16) {
            int   tok = tok_sh[s];
            float w   = w_sh[s];
            float4 v  = __ldg(emb4 + (size_t)tok * (D / 4) + dq);
            acc.x += w * v.x;
            acc.y += w * v.y;
            acc.z += w * v.z;
            acc.w += w * v.w;
        }
        red4[sg][dq] = acc;
        __syncthreads();

        if (tid < D / 4) {
            float4 r = red4[0][tid];
            #pragma unroll
            for (int k = 1; k < 16; k++) {
                float4 a = red4[k][tid];
                r.x += a.x; r.y += a.y; r.z += a.z; r.w += a.w;
            }
            reinterpret_cast<float4*>(g_partial + ((size_t)b * CHUNKS + chunk) * D)[tid] = r;
        }
    }

    // ---------------- phase 3: last-CTA ticket ----------------
    __threadfence();
    __syncthreads();
    if (tid == 0) {
        int prev = atomicAdd(&g_count[b], 1);
        last_sh = (prev == CHUNKS - 1);
        if (last_sh) g_count[b] = 0;         // self-reset for graph replay
    }
    __syncthreads();
    if (!last_sh) return;

    // ---------------- phase 4: MLP tail (quad-per-output, no staging) ------
    if (tid < D) {
        const float* p = g_partial + (size_t)b * CHUNKS * D;
        float s = __ldcg(p + tid) + __ldcg(p + D + tid) +
                  __ldcg(p + 2 * D + tid) + __ldcg(p + 3 * D + tid);
        reinterpret_cast<float*>(pls4)[tid] = s;
    }
    __syncthreads();

    const int q = tid >> 2;      // quad id, 0..255
    const int s = tid & 3;       // quad lane

    // L1: 100 outputs -> one round.
    if (q < 128) {
        int j  = q;
        int jj = j < H1 ? j : H1 - 1;
        const float4* w = reinterpret_cast<const float4*>(W1) + (size_t)jj * (D / 4);
        float a = 0.f;
        #pragma unroll
        for (int i = 0; i < 16; i++) {
            float4 wv = __ldg(w + 4 * i + s);
            float4 pv = pls4[4 * i + s];
            a += wv.x * pv.x + wv.y * pv.y + wv.z * pv.z + wv.w * pv.w;
        }
        a += __shfl_xor_sync(0xffffffffu, a, 1);
        a += __shfl_xor_sync(0xffffffffu, a, 2);
        if (s == 0 && j < H1)
            reinterpret_cast<float*>(h1s4)[j] = fmaxf(a + __ldg(b1 + j), 0.f);
    }
    __syncthreads();

    // L2: 150 outputs -> one round over 256 quads.
    {
        int j  = q;
        int jj = j < H2 ? j : H2 - 1;
        const float4* w = reinterpret_cast<const float4*>(W2 + (size_t)jj * H1);
        float a = 0.f;
        #pragma unroll
        for (int idx = s; idx < 25; idx += 4) {
            float4 wv = __ldg(w + idx);
            float4 hv = h1s4[idx];
            a += wv.x * hv.x + wv.y * hv.y + wv.z * hv.z + wv.w * hv.w;
        }
        a += __shfl_xor_sync(0xffffffffu, a, 1);
        a += __shfl_xor_sync(0xffffffffu, a, 2);
        if (s == 0 && j < H2) h2s[j] = fmaxf(a + __ldg(b2 + j), 0.f);
    }
    __syncthreads();

    // L3: warp per logit, shfl reduce.
    if (tid < 64) {
        const int o    = tid >> 5;
        const int lane = tid & 31;
        const float* w = W3 + (size_t)o * H2;
        float a = 0.f;
        #pragma unroll
        for (int d = lane; d < H2; d += 32) a += h2s[d] * __ldg(w + d);
        #pragma unroll
        for (int off = 16; off; off >>= 1) a += __shfl_xor_sync(0xffffffffu, a, off);
        if (lane == 0) zs[o] = a + __ldg(b3 + o);
    }
    __syncthreads();

    if (tid == 0) {
        float z0 = zs[0], z1 = zs[1];
        float m  = fmaxf(z0, z1);
        float e0 = expf(z0 - m);
        float e1 = expf(z1 - m);
        float inv = 1.0f / (e0 + e1);
        out[b * 2 + 0] = e0 * inv;
        out[b * 2 + 1] = e1 * inv;
    }
}

extern "C" void kernel_launch(void* const* d_in, const int* in_sizes, int n_in,
                              void* d_out, int out_size) {
    const int*   x   = (const int*)  d_in[0];
    const float* emb = (const float*)d_in[1];
    const float* idf = (const float*)d_in[2];
    const float* W1  = (const float*)d_in[3];
    const float* b1  = (const float*)d_in[4];
    const float* W2  = (const float*)d_in[5];
    const float* b2  = (const float*)d_in[6];
    const float* W3  = (const float*)d_in[7];
    const float* b3  = (const float*)d_in[8];
    float* out = (float*)d_out;

    fused_kernel<<<BATCH * CHUNKS, NT>>>(x, emb, idf,
                                         W1, b1, W2, b2, W3, b3, out);
}

// round 17
// speedup vs baseline: 1.0082x; 1.0082x over previous
#include <cuda_runtime.h>
#include <cuda_bf16.h>

#define SEQ    2048
#define BATCH  64
#define D      256
#define CHUNKS 4
#define CHUNK_S (SEQ / CHUNKS)   // 512
#define HSIZE  4096
#define HMASK  (HSIZE - 1)
#define NT     1024              // 2 CTAs/SM, 64 warps/SM

#define H1 100
#define H2 150

// Scratch (device globals — no allocations allowed)
__device__ float g_partial[BATCH * CHUNKS * D];
__device__ int   g_count[BATCH];   // zero-init at load; self-resetting

__device__ __forceinline__ unsigned hash_tok(int tok) {
    return ((unsigned)tok * 2654435761u) & HMASK;
}

// ---------------------------------------------------------------------------
// Single fused kernel (R15 structure). 256 CTAs x 1024 threads.
// Phase 1: packed smem histogram (single-CAS fast path) + weighted embedding
//          gather (one stream, 32 LDG.128/thread, unroll 8).
// Phase 2: last CTA per batch runs the MLP tail (quad-per-output, direct
//          float4 weight reads, no smem staging).
// ---------------------------------------------------------------------------
__global__ __launch_bounds__(NT, 2)
void fused_kernel(const int*   __restrict__ x,
                  const float* __restrict__ emb,
                  const float* __restrict__ idf,
                  const float* __restrict__ W1, const float* __restrict__ b1,
                  const float* __restrict__ W2, const float* __restrict__ b2,
                  const float* __restrict__ W3, const float* __restrict__ b3,
                  float* __restrict__ out) {
    __shared__ int      tok_sh[SEQ];        // 8 KB
    __shared__ unsigned htab[HSIZE];        // 16 KB packed (tok<<16)|cnt
    __shared__ float    w_sh[CHUNK_S];      // 2 KB
    __shared__ float4   red4[16][D / 4];    // 16 KB
    // tail buffers
    __shared__ float4   pls4[D / 4];
    __shared__ float4   h1s4[26];
    __shared__ float    h2s[H2 + 2];
    __shared__ float    zs[2];
    __shared__ int      last_sh;

    const int tid   = threadIdx.x;
    const int b     = blockIdx.x >> 2;      // batch
    const int chunk = blockIdx.x & 3;       // seq chunk

    // ---------------- phase 1: pool ----------------
    #pragma unroll
    for (int i = tid; i < HSIZE; i += NT) htab[i] = 0u;
    #pragma unroll
    for (int s = tid; s < SEQ; s += NT) tok_sh[s] = __ldcs(&x[s * BATCH + b]);
    __syncthreads();

    // insert: single-CAS fast path — claim (tok<<16)|1 in one atomic; only
    // duplicates (rare: ~2% of positions) pay the extra atomicAdd.
    #pragma unroll
    for (int s = tid; s < SEQ; s += NT) {
        int tok = tok_sh[s];
        if (tok == 0) continue;
        unsigned key = (unsigned)tok << 16;
        unsigned h = hash_tok(tok);
        while (true) {
            unsigned prev = atomicCAS(&htab[h], 0u, key | 1u);
            if (prev == 0u) break;
            if ((prev >> 16) == (unsigned)tok) { atomicAdd(&htab[h], 1u); break; }
            h = (h + 1) & HMASK;
        }
    }
    __syncthreads();

    const int base = chunk * CHUNK_S;
    if (tid < CHUNK_S) {
        int tok = tok_sh[base + tid];
        float w = 0.0f;
        if (tok != 0) {
            unsigned h = hash_tok(tok);
            unsigned v;
            while (((v = htab[h]) >> 16) != (unsigned)tok) h = (h + 1) & HMASK;
            w = (float)(v & 0xffffu) * __ldg(&idf[tok]);
        }
        w_sh[tid] = w;
    }
    __syncthreads();

    {
        // gather: sg in [0,16) picks s ≡ sg (mod 16); dq in [0,64) float4 dim.
        const int sg = tid >> 6;
        const int dq = tid & 63;
        const float4* emb4 = reinterpret_cast<const float4*>(emb);

        float4 acc = make_float4(0.f, 0.f, 0.f, 0.f);
        #pragma unroll 8
        for (int s = sg; s < CHUNK_S; s += 16) {
            int   tok = tok_sh[base + s];
            float w   = w_sh[s];
            float4 v  = __ldg(emb4 + (size_t)tok * (D / 4) + dq);
            acc.x += w * v.x;
            acc.y += w * v.y;
            acc.z += w * v.z;
            acc.w += w * v.w;
        }
        red4[sg][dq] = acc;
        __syncthreads();

        if (tid < D / 4) {
            float4 r = red4[0][tid];
            #pragma unroll
            for (int k = 1; k < 16; k++) {
                float4 a = red4[k][tid];
                r.x += a.x; r.y += a.y; r.z += a.z; r.w += a.w;
            }
            reinterpret_cast<float4*>(g_partial + ((size_t)b * CHUNKS + chunk) * D)[tid] = r;
        }
    }

    // ---------------- phase 2: last-CTA ticket ----------------
    __threadfence();
    __syncthreads();
    if (tid == 0) {
        int prev = atomicAdd(&g_count[b], 1);
        last_sh = (prev == CHUNKS - 1);
        if (last_sh) g_count[b] = 0;       // self-reset for graph replay
    }
    __syncthreads();
    if (!last_sh) return;

    // ---------------- phase 3: MLP tail (quad-per-output, no staging) ------
    if (tid < D) {
        const float* p = g_partial + (size_t)b * CHUNKS * D;
        float s = __ldcg(p + tid) + __ldcg(p + D + tid) +
                  __ldcg(p + 2 * D + tid) + __ldcg(p + 3 * D + tid);
        reinterpret_cast<float*>(pls4)[tid] = s;
    }
    __syncthreads();

    const int q = tid >> 2;      // quad id, 0..255
    const int s = tid & 3;       // quad lane

    // L1: 100 outputs -> one round over 256 quads.
    {
        int j  = q;
        int jj = j < H1 ? j : H1 - 1;
        const float4* w = reinterpret_cast<const float4*>(W1) + (size_t)jj * (D / 4);
        float a = 0.f;
        #pragma unroll
        for (int i = 0; i < 16; i++) {
            float4 wv = __ldg(w + 4 * i + s);
            float4 pv = pls4[4 * i + s];
            a += wv.x * pv.x + wv.y * pv.y + wv.z * pv.z + wv.w * pv.w;
        }
        a += __shfl_xor_sync(0xffffffffu, a, 1);
        a += __shfl_xor_sync(0xffffffffu, a, 2);
        if (s == 0 && j < H1)
            reinterpret_cast<float*>(h1s4)[j] = fmaxf(a + __ldg(b1 + j), 0.f);
    }
    __syncthreads();

    // L2: 150 outputs -> one round over 256 quads.
    {
        int j  = q;
        int jj = j < H2 ? j : H2 - 1;
        const float4* w = reinterpret_cast<const float4*>(W2 + (size_t)jj * H1);
        float a = 0.f;
        #pragma unroll
        for (int idx = s; idx < 25; idx += 4) {
            float4 wv = __ldg(w + idx);
            float4 hv = h1s4[idx];
            a += wv.x * hv.x + wv.y * hv.y + wv.z * hv.z + wv.w * hv.w;
        }
        a += __shfl_xor_sync(0xffffffffu, a, 1);
        a += __shfl_xor_sync(0xffffffffu, a, 2);
        if (s == 0 && j < H2) h2s[j] = fmaxf(a + __ldg(b2 + j), 0.f);
    }
    __syncthreads();

    // L3: warp per logit (threads 0-63), shfl reduce.
    if (tid < 64) {
        const int o    = tid >> 5;
        const int lane = tid & 31;
        const float* w = W3 + (size_t)o * H2;
        float a = 0.f;
        #pragma unroll
        for (int d = lane; d < H2; d += 32) a += h2s[d] * __ldg(w + d);
        #pragma unroll
        for (int off = 16; off; off >>= 1) a += __shfl_xor_sync(0xffffffffu, a, off);
        if (lane == 0) zs[o] = a + __ldg(b3 + o);
    }
    __syncthreads();

    if (tid == 0) {
        float z0 = zs[0], z1 = zs[1];
        float m  = fmaxf(z0, z1);
        float e0 = expf(z0 - m);
        float e1 = expf(z1 - m);
        float inv = 1.0f / (e0 + e1);
        out[b * 2 + 0] = e0 * inv;
        out[b * 2 + 1] = e1 * inv;
    }
}

extern "C" void kernel_launch(void* const* d_in, const int* in_sizes, int n_in,
                              void* d_out, int out_size) {
    const int*   x   = (const int*)  d_in[0];
    const float* emb = (const float*)d_in[1];
    const float* idf = (const float*)d_in[2];
    const float* W1  = (const float*)d_in[3];
    const float* b1  = (const float*)d_in[4];
    const float* W2  = (const float*)d_in[5];
    const float* b2  = (const float*)d_in[6];
    const float* W3  = (const float*)d_in[7];
    const float* b3  = (const float*)d_in[8];
    float* out = (float*)d_out;

    fused_kernel<<<BATCH * CHUNKS, NT>>>(x, emb, idf,
                                         W1, b1, W2, b2, W3, b3, out);
}